// round 2
// baseline (speedup 1.0000x reference)
#include <cuda_runtime.h>
#include <cstdint>

#define N_NODES 100000
#define D_FEAT  256
#define ATT     256
#define KC      2048     // K range per split CTA
#define NSPLIT  49       // ceil(100000/2048); last split gets 1696 (=53*32, exact)
#define KT      32       // K per SMEM tile

// Scratch (allocation-free: __device__ globals)
__device__ float T_dev[3 * ATT * D_FEAT];     // 768 KB partial-T accumulator
__device__ float beta_dev[3 * D_FEAT];

__device__ __forceinline__ uint32_t f2tf32(float x) {
    uint32_t r;
    asm("cvt.rna.tf32.f32 %0, %1;" : "=r"(r) : "f"(x));
    return r;
}

__global__ void zeroT_kernel() {
    int i = blockIdx.x * blockDim.x + threadIdx.x;
    if (i < 3 * ATT * D_FEAT) T_dev[i] = 0.0f;
}

// grid: (12 tile-combos, NSPLIT), block: 256 threads (8 warps = 2 Mwarp x 4 Nwarp)
// CTA tile: 128(M) x 128(N), warp tile 64x32, mma m16n8k8 tf32.
__global__ __launch_bounds__(256, 2)
void gemm_partial_kernel(const float* __restrict__ x1,
                         const float* __restrict__ x2,
                         const float* __restrict__ x3,
                         const float* __restrict__ W)
{
    // A = W tile [128 x 32], stride 36 (conflict-free frag loads: bank = lane)
    // B = x tile [32 x 128], stride 132 (2-way conflict on frag loads, stores coalesced)
    __shared__ __align__(16) uint32_t As[128 * 36];
    __shared__ __align__(16) uint32_t Bs[KT * 132];

    const int tcomb = blockIdx.x;
    const int v  = tcomb >> 2;
    const int mt = (tcomb >> 1) & 1;
    const int nt = tcomb & 1;
    const float* __restrict__ X = (v == 0) ? x1 : ((v == 1) ? x2 : x3);

    const int m0 = mt * 128;
    const int n0 = nt * 128;
    const int kbase = blockIdx.y * KC;
    const int kend  = min(kbase + KC, N_NODES);

    const int tid  = threadIdx.x;
    const int lane = tid & 31;
    const int w    = tid >> 5;
    const int wm   = w & 1;        // 0/1 -> 64 M-rows each
    const int wn   = w >> 1;       // 0..3 -> 32 N-cols each
    const int g    = lane >> 2;    // groupID
    const int tig  = lane & 3;     // thread-in-group

    float acc[4][4][4];
    #pragma unroll
    for (int i = 0; i < 4; i++)
        #pragma unroll
        for (int j = 0; j < 4; j++)
            #pragma unroll
            for (int r = 0; r < 4; r++) acc[i][j][r] = 0.0f;

    // Staging thread mapping
    const int ac = tid & 7;        // A float4-col (0..7)
    const int ai = tid >> 3;       // A row base (0..31)
    const int bc = tid & 31;       // B float4-col (0..31)
    const int bj = tid >> 5;       // B row base (0..7)

    for (int k0 = kbase; k0 < kend; k0 += KT) {
        __syncthreads();
        // ---- load A tile: W[m0+i][k0 + 4*ac .. +3], i in [0,128) ----
        #pragma unroll
        for (int it = 0; it < 4; it++) {
            int i = ai + it * 32;
            const float4 a4 = *reinterpret_cast<const float4*>(
                &W[(size_t)(m0 + i) * N_NODES + k0 + ac * 4]);
            uint32_t* dst = &As[i * 36 + ac * 4];
            dst[0] = f2tf32(a4.x); dst[1] = f2tf32(a4.y);
            dst[2] = f2tf32(a4.z); dst[3] = f2tf32(a4.w);
        }
        // ---- load B tile: X[k0+j][n0 + 4*bc .. +3], j in [0,32) ----
        #pragma unroll
        for (int it = 0; it < 4; it++) {
            int j = bj + it * 8;
            const float4 b4 = *reinterpret_cast<const float4*>(
                &X[(size_t)(k0 + j) * D_FEAT + n0 + bc * 4]);
            uint32_t* dst = &Bs[j * 132 + bc * 4];
            dst[0] = f2tf32(b4.x); dst[1] = f2tf32(b4.y);
            dst[2] = f2tf32(b4.z); dst[3] = f2tf32(b4.w);
        }
        __syncthreads();

        // ---- compute: 4 k-steps of 8 ----
        #pragma unroll
        for (int kk = 0; kk < KT / 8; kk++) {
            uint32_t a[4][4], b[4][2];
            #pragma unroll
            for (int fm = 0; fm < 4; fm++) {
                int mrow = wm * 64 + fm * 16 + g;
                int kcol = kk * 8 + tig;
                a[fm][0] = As[mrow * 36 + kcol];
                a[fm][1] = As[(mrow + 8) * 36 + kcol];
                a[fm][2] = As[mrow * 36 + kcol + 4];
                a[fm][3] = As[(mrow + 8) * 36 + kcol + 4];
            }
            #pragma unroll
            for (int fn = 0; fn < 4; fn++) {
                int ncol = wn * 32 + fn * 8 + g;
                b[fn][0] = Bs[(kk * 8 + tig) * 132 + ncol];
                b[fn][1] = Bs[(kk * 8 + tig + 4) * 132 + ncol];
            }
            #pragma unroll
            for (int fm = 0; fm < 4; fm++)
                #pragma unroll
                for (int fn = 0; fn < 4; fn++)
                    asm volatile(
                        "mma.sync.aligned.m16n8k8.row.col.f32.tf32.tf32.f32 "
                        "{%0,%1,%2,%3}, {%4,%5,%6,%7}, {%8,%9}, {%0,%1,%2,%3};"
                        : "+f"(acc[fm][fn][0]), "+f"(acc[fm][fn][1]),
                          "+f"(acc[fm][fn][2]), "+f"(acc[fm][fn][3])
                        : "r"(a[fm][0]), "r"(a[fm][1]), "r"(a[fm][2]), "r"(a[fm][3]),
                          "r"(b[fn][0]), "r"(b[fn][1]));
        }
    }

    // ---- accumulate partials into global T ----
    float* T = &T_dev[v * ATT * D_FEAT];
    #pragma unroll
    for (int fm = 0; fm < 4; fm++) {
        int mrow = m0 + wm * 64 + fm * 16 + g;
        #pragma unroll
        for (int fn = 0; fn < 4; fn++) {
            int ncol = n0 + wn * 32 + fn * 8 + 2 * tig;
            atomicAdd(&T[mrow * D_FEAT + ncol],           acc[fm][fn][0]);
            atomicAdd(&T[mrow * D_FEAT + ncol + 1],       acc[fm][fn][1]);
            atomicAdd(&T[(mrow + 8) * D_FEAT + ncol],     acc[fm][fn][2]);
            atomicAdd(&T[(mrow + 8) * D_FEAT + ncol + 1], acc[fm][fn][3]);
        }
    }
}

// One block of 256 threads: per feature column d, project tanh(T) with h_n,
// softmax over the 3 views, write beta.
__global__ void finalize_kernel(const float* __restrict__ hn) {
    __shared__ float hs[ATT];
    int d = threadIdx.x;
    hs[d] = hn[d];
    __syncthreads();

    float s[3];
    #pragma unroll
    for (int v = 0; v < 3; v++) {
        const float* T = &T_dev[v * ATT * D_FEAT];
        float a = 0.0f;
        for (int i = 0; i < ATT; i++)
            a += hs[i] * tanhf(T[i * D_FEAT + d]);
        s[v] = a;
    }
    float m  = fmaxf(s[0], fmaxf(s[1], s[2]));
    float e0 = expf(s[0] - m), e1 = expf(s[1] - m), e2 = expf(s[2] - m);
    float inv = 1.0f / (e0 + e1 + e2);
    beta_dev[0 * D_FEAT + d] = e0 * inv;
    beta_dev[1 * D_FEAT + d] = e1 * inv;
    beta_dev[2 * D_FEAT + d] = e2 * inv;
}

// Streaming weighted sum: out[n,d] = b0[d]*x1 + b1[d]*x2 + b2[d]*x3 (float4)
__global__ void weighted_kernel(const float4* __restrict__ x1,
                                const float4* __restrict__ x2,
                                const float4* __restrict__ x3,
                                float4* __restrict__ out)
{
    __shared__ __align__(16) float b[3 * D_FEAT];
    b[threadIdx.x]       = beta_dev[threadIdx.x];
    b[256 + threadIdx.x] = beta_dev[256 + threadIdx.x];
    b[512 + threadIdx.x] = beta_dev[512 + threadIdx.x];
    __syncthreads();

    long idx = (long)blockIdx.x * blockDim.x + threadIdx.x;
    if (idx >= (long)N_NODES * D_FEAT / 4) return;
    int c = (int)(idx & 63);   // float4 column within the 256-wide row

    const float4* bf = reinterpret_cast<const float4*>(b);
    float4 B0 = bf[c], B1 = bf[64 + c], B2 = bf[128 + c];
    float4 v1 = x1[idx], v2 = x2[idx], v3 = x3[idx];

    float4 o;
    o.x = B0.x * v1.x + B1.x * v2.x + B2.x * v3.x;
    o.y = B0.y * v1.y + B1.y * v2.y + B2.y * v3.y;
    o.z = B0.z * v1.z + B1.z * v2.z + B2.z * v3.z;
    o.w = B0.w * v1.w + B1.w * v2.w + B2.w * v3.w;
    out[idx] = o;
}

extern "C" void kernel_launch(void* const* d_in, const int* in_sizes, int n_in,
                              void* d_out, int out_size)
{
    const float* x1 = (const float*)d_in[0];
    const float* x2 = (const float*)d_in[1];
    const float* x3 = (const float*)d_in[2];
    const float* W  = (const float*)d_in[3];
    const float* hn = (const float*)d_in[4];

    zeroT_kernel<<<192, 1024>>>();
    dim3 grid(12, NSPLIT);
    gemm_partial_kernel<<<grid, 256>>>(x1, x2, x3, W);
    finalize_kernel<<<1, 256>>>(hn);
    weighted_kernel<<<25000, 256>>>((const float4*)x1, (const float4*)x2,
                                    (const float4*)x3, (float4*)d_out);
}

// round 8
// speedup vs baseline: 1.3514x; 1.3514x over previous
#include <cuda_runtime.h>
#include <cstdint>

#define N_NODES 100000
#define D_FEAT  256
#define ATT     256
#define NSPLIT  24            // 3125 K-tiles of 32 rows split 24 ways

// SMEM layout (u32 units): per stage: A 128x36 = 4608, B 32x264 = 8448
#define A_STRIDE 36
#define B_STRIDE 264
#define STAGE_U32 (4608 + 8448)          // 13056 u32 = 52224 B
#define SMEM_TOTAL (2 * STAGE_U32 * 4)   // 104448 B

// Scratch (allocation-free)
__device__ float T_dev[3 * ATT * D_FEAT];
__device__ float beta_dev[3 * D_FEAT];

__device__ __forceinline__ uint32_t smem_u32(const void* p) {
    uint32_t a;
    asm("{ .reg .u64 t; cvta.to.shared.u64 t, %1; cvt.u32.u64 %0, t; }" : "=r"(a) : "l"(p));
    return a;
}
__device__ __forceinline__ void cp_async16(uint32_t dst, const void* src) {
    asm volatile("cp.async.cg.shared.global [%0], [%1], 16;" :: "r"(dst), "l"(src) : "memory");
}

__global__ void zeroT_kernel() {
    int i = blockIdx.x * blockDim.x + threadIdx.x;
    if (i < 3 * ATT * D_FEAT) T_dev[i] = 0.0f;
}

// grid (6 combos: v x mt, 24 K-splits), 512 threads = 16 warps (2 Mwarp x 8 Nwarp).
// CTA tile 128(M) x 256(N), warp tile 64x32, mma m16n8k8 tf32 (raw fp32 bits).
__global__ __launch_bounds__(512, 1)
void gemm_mma_kernel(const float* __restrict__ x1,
                     const float* __restrict__ x2,
                     const float* __restrict__ x3,
                     const float* __restrict__ W)
{
    extern __shared__ __align__(16) uint32_t smem[];
    const uint32_t sb = smem_u32(smem);

    const int bx = blockIdx.x;
    const int v  = bx >> 1;
    const int mt = bx & 1;
    const float* __restrict__ X = (v == 0) ? x1 : ((v == 1) ? x2 : x3);
    const int m0 = mt * 128;

    const int split  = blockIdx.y;
    const int tstart = split * 130 + min(split, 5);   // 3125 = 24*130 + 5
    const int NT     = 130 + (split < 5 ? 1 : 0);

    const int tid  = threadIdx.x;
    const int lane = tid & 31;
    const int w    = tid >> 5;
    const int wm   = w & 1;        // 0/1 -> 64 M-rows
    const int wn   = w >> 1;       // 0..7 -> 32 N-cols
    const int g    = lane >> 2;    // groupID (0..7)
    const int tig  = lane & 3;     // thread-in-group

    float acc[4][4][4];
    #pragma unroll
    for (int i = 0; i < 4; i++)
        #pragma unroll
        for (int j = 0; j < 4; j++)
            #pragma unroll
            for (int r = 0; r < 4; r++) acc[i][j][r] = 0.0f;

    // Staging maps (raw fp32 bits; tf32 MMA ignores low mantissa bits)
    // A: 1024 x 16B chunks: r = flat>>3 (0..127), c = flat&7
    // B: 2048 x 16B chunks: j = flat>>6 (0..31),  c4 = flat&63
    const int ar0 = tid >> 3, ac0 = tid & 7;
    const int bj0 = tid >> 6, bc0 = tid & 63;

    // issue stage loads for tile index tt
    auto issue = [&](int tt) {
        const int s = tt & 1;
        const int k0 = (tstart + tt) * 32;
        const uint32_t a_base = sb + (s * STAGE_U32) * 4;
        const uint32_t b_base = a_base + 4608 * 4;
        #pragma unroll
        for (int i = 0; i < 2; i++) {
            int r = ar0 + i * 64;
            cp_async16(a_base + (r * A_STRIDE + ac0 * 4) * 4,
                       W + (size_t)(m0 + r) * N_NODES + k0 + ac0 * 4);
        }
        #pragma unroll
        for (int i = 0; i < 4; i++) {
            int j = bj0 + i * 8;
            cp_async16(b_base + (j * B_STRIDE + bc0 * 4) * 4,
                       X + (size_t)(k0 + j) * D_FEAT + bc0 * 4);
        }
        asm volatile("cp.async.commit_group;" ::: "memory");
    };

    issue(0);

    for (int t = 0; t < NT; t++) {
        if (t + 1 < NT) {
            issue(t + 1);
            asm volatile("cp.async.wait_group 1;" ::: "memory");
        } else {
            asm volatile("cp.async.wait_group 0;" ::: "memory");
        }
        __syncthreads();   // stage t data visible to all

        const int s = t & 1;
        const uint32_t* As = smem + s * STAGE_U32;
        const uint32_t* Bs = As + 4608;

        #pragma unroll
        for (int kk = 0; kk < 4; kk++) {
            uint32_t a[4][4], b[4][2];
            #pragma unroll
            for (int fm = 0; fm < 4; fm++) {
                int mrow = wm * 64 + fm * 16 + g;
                int kcol = kk * 8 + tig;
                a[fm][0] = As[mrow * A_STRIDE + kcol];
                a[fm][1] = As[(mrow + 8) * A_STRIDE + kcol];
                a[fm][2] = As[mrow * A_STRIDE + kcol + 4];
                a[fm][3] = As[(mrow + 8) * A_STRIDE + kcol + 4];
            }
            #pragma unroll
            for (int fn = 0; fn < 4; fn++) {
                int ncol = wn * 32 + fn * 8 + g;
                b[fn][0] = Bs[(kk * 8 + tig) * B_STRIDE + ncol];
                b[fn][1] = Bs[(kk * 8 + tig + 4) * B_STRIDE + ncol];
            }
            #pragma unroll
            for (int fm = 0; fm < 4; fm++)
                #pragma unroll
                for (int fn = 0; fn < 4; fn++)
                    asm volatile(
                        "mma.sync.aligned.m16n8k8.row.col.f32.tf32.tf32.f32 "
                        "{%0,%1,%2,%3}, {%4,%5,%6,%7}, {%8,%9}, {%0,%1,%2,%3};"
                        : "+f"(acc[fm][fn][0]), "+f"(acc[fm][fn][1]),
                          "+f"(acc[fm][fn][2]), "+f"(acc[fm][fn][3])
                        : "r"(a[fm][0]), "r"(a[fm][1]), "r"(a[fm][2]), "r"(a[fm][3]),
                          "r"(b[fn][0]), "r"(b[fn][1]));
        }
        __syncthreads();   // compute(t) done; next iter may overwrite stage t&1
    }

    // accumulate partials into global T
    float* Tg = &T_dev[v * ATT * D_FEAT];
    #pragma unroll
    for (int fm = 0; fm < 4; fm++) {
        int mrow = m0 + wm * 64 + fm * 16 + g;
        #pragma unroll
        for (int fn = 0; fn < 4; fn++) {
            int ncol = wn * 32 + fn * 8 + 2 * tig;
            atomicAdd(&Tg[mrow * D_FEAT + ncol],           acc[fm][fn][0]);
            atomicAdd(&Tg[mrow * D_FEAT + ncol + 1],       acc[fm][fn][1]);
            atomicAdd(&Tg[(mrow + 8) * D_FEAT + ncol],     acc[fm][fn][2]);
            atomicAdd(&Tg[(mrow + 8) * D_FEAT + ncol + 1], acc[fm][fn][3]);
        }
    }
}

// grid 8 x 256 threads: 32 d-columns per block, 8 K-chunks per column.
__global__ void finalize_kernel(const float* __restrict__ hn) {
    __shared__ float hs[ATT];
    __shared__ float red[3][8][32];
    int tid = threadIdx.x;
    hs[tid] = hn[tid];
    __syncthreads();

    int dl = tid & 31, ch = tid >> 5;
    int d  = blockIdx.x * 32 + dl;
    #pragma unroll
    for (int v = 0; v < 3; v++) {
        const float* Tg = &T_dev[v * ATT * D_FEAT];
        float a = 0.0f;
        #pragma unroll 8
        for (int i = ch * 32; i < ch * 32 + 32; i++)
            a += hs[i] * tanhf(Tg[i * D_FEAT + d]);
        red[v][ch][dl] = a;
    }
    __syncthreads();
    if (ch == 0) {
        float s[3];
        #pragma unroll
        for (int v = 0; v < 3; v++) {
            float a = 0.0f;
            #pragma unroll
            for (int c = 0; c < 8; c++) a += red[v][c][dl];
            s[v] = a;
        }
        float m  = fmaxf(s[0], fmaxf(s[1], s[2]));
        float e0 = expf(s[0] - m), e1 = expf(s[1] - m), e2 = expf(s[2] - m);
        float inv = 1.0f / (e0 + e1 + e2);
        beta_dev[0 * D_FEAT + d] = e0 * inv;
        beta_dev[1 * D_FEAT + d] = e1 * inv;
        beta_dev[2 * D_FEAT + d] = e2 * inv;
    }
}

// Streaming weighted sum: out[n,d] = b0[d]*x1 + b1[d]*x2 + b2[d]*x3 (float4)
__global__ void weighted_kernel(const float4* __restrict__ x1,
                                const float4* __restrict__ x2,
                                const float4* __restrict__ x3,
                                float4* __restrict__ out)
{
    __shared__ __align__(16) float b[3 * D_FEAT];
    b[threadIdx.x]       = beta_dev[threadIdx.x];
    b[256 + threadIdx.x] = beta_dev[256 + threadIdx.x];
    b[512 + threadIdx.x] = beta_dev[512 + threadIdx.x];
    __syncthreads();

    long idx = (long)blockIdx.x * blockDim.x + threadIdx.x;
    if (idx >= (long)N_NODES * D_FEAT / 4) return;
    int c = (int)(idx & 63);

    const float4* bf = reinterpret_cast<const float4*>(b);
    float4 B0 = bf[c], B1 = bf[64 + c], B2 = bf[128 + c];
    float4 v1 = x1[idx], v2 = x2[idx], v3 = x3[idx];

    float4 o;
    o.x = B0.x * v1.x + B1.x * v2.x + B2.x * v3.x;
    o.y = B0.y * v1.y + B1.y * v2.y + B2.y * v3.y;
    o.z = B0.z * v1.z + B1.z * v2.z + B2.z * v3.z;
    o.w = B0.w * v1.w + B1.w * v2.w + B2.w * v3.w;
    out[idx] = o;
}

extern "C" void kernel_launch(void* const* d_in, const int* in_sizes, int n_in,
                              void* d_out, int out_size)
{
    const float* x1 = (const float*)d_in[0];
    const float* x2 = (const float*)d_in[1];
    const float* x3 = (const float*)d_in[2];
    const float* W  = (const float*)d_in[3];
    const float* hn = (const float*)d_in[4];

    cudaFuncSetAttribute(gemm_mma_kernel, cudaFuncAttributeMaxDynamicSharedMemorySize, SMEM_TOTAL);

    zeroT_kernel<<<192, 1024>>>();
    gemm_mma_kernel<<<dim3(6, NSPLIT), 512, SMEM_TOTAL>>>(x1, x2, x3, W);
    finalize_kernel<<<8, 256>>>(hn);
    weighted_kernel<<<25000, 256>>>((const float4*)x1, (const float4*)x2,
                                    (const float4*)x3, (float4*)d_out);
}